// round 1
// baseline (speedup 1.0000x reference)
#include <cuda_runtime.h>
#include <cstddef>
#include <cstdint>

// Problem constants
#define NB   256      // batch
#define NU   8        // in_units
#define NI   1152     // in_size
#define NJ   10       // out_units
#define ND   16       // out_size
#define NJD  (NJ*ND)  // 160

// Scratch (device globals; allocation-free per harness rules)
__device__ float g_U[(size_t)NB * NJD * NI];   // u_hat, layout [b][jd][i]  (188.7 MB)
__device__ float g_s[NB * NJD];
__device__ float g_v[NB * NJD];
__device__ float g_b[NI * NJ];
__device__ float g_c[NI * NJ];
__device__ float g_uv[NI * NJ];                // zero-initialized at load; kept zero at launch boundaries

// ---------------------------------------------------------------------------
// Kernel 1: u_hat[b,jd,i] = sum_u W[i,jd,u] * x[b,u,i]
// grid (36 i-tiles, 4 jd-tiles, 4 b-tiles), block 256 (8 warps).
// Warp w owns jd = jt*40 + w*5 .. +5 ; lane owns i. W cached in 40 regs, x in 8.
// ---------------------------------------------------------------------------
__global__ __launch_bounds__(256) void uhat_kernel(const float* __restrict__ x,
                                                   const float* __restrict__ W) {
    const int lane = threadIdx.x & 31;
    const int w    = threadIdx.x >> 5;
    const int i    = blockIdx.x * 32 + lane;
    const int jd0  = blockIdx.y * 40 + w * 5;
    const int b0   = blockIdx.z * 64;

    float Wr[5][8];
#pragma unroll
    for (int q = 0; q < 5; q++) {
        const float* wp = W + ((size_t)i * NJD + (jd0 + q)) * NU;
#pragma unroll
        for (int u = 0; u < 8; u++) Wr[q][u] = __ldg(wp + u);
    }

    const float* xbase = x + (size_t)b0 * NU * NI + i;
    float* ubase = g_U + ((size_t)b0 * NJD + jd0) * NI + i;

    for (int bb = 0; bb < 64; bb++) {
        float xr[8];
        const float* xp = xbase + (size_t)bb * NU * NI;
#pragma unroll
        for (int u = 0; u < 8; u++) xr[u] = __ldg(xp + (size_t)u * NI);

        float* up = ubase + (size_t)bb * NJD * NI;
#pragma unroll
        for (int q = 0; q < 5; q++) {
            float acc = 0.f;
#pragma unroll
            for (int u = 0; u < 8; u++) acc = fmaf(Wr[q][u], xr[u], acc);
            up[(size_t)q * NI] = acc;
        }
    }
}

// ---------------------------------------------------------------------------
// Kernel 2: routing softmax over i, fused with b-update and uv reset.
//   bnew[i,j] = (init ? 1.0 : b[i,j]) + uv[i,j]/B ;  uv[i,j] = 0
//   c[:,j]    = softmax_i(bnew[:,j])
// grid 10 (one block per j), block 128.
// ---------------------------------------------------------------------------
__global__ void softmax_kernel(int init) {
    const int j = blockIdx.x;
    const int t = threadIdx.x;
    __shared__ float sb[NI];
    __shared__ float red[128];

    float mx = -1e30f;
    for (int i = t; i < NI; i += 128) {
        float base = init ? 1.0f : g_b[i * NJ + j];
        float bn = base + g_uv[i * NJ + j] * (1.0f / (float)NB);
        g_b[i * NJ + j]  = bn;
        g_uv[i * NJ + j] = 0.0f;
        sb[i] = bn;
        mx = fmaxf(mx, bn);
    }
    red[t] = mx;
    __syncthreads();
    for (int s = 64; s > 0; s >>= 1) {
        if (t < s) red[t] = fmaxf(red[t], red[t + s]);
        __syncthreads();
    }
    mx = red[0];
    __syncthreads();

    float sum = 0.f;
    for (int i = t; i < NI; i += 128) {
        float e = expf(sb[i] - mx);
        sb[i] = e;
        sum += e;
    }
    red[t] = sum;
    __syncthreads();
    for (int s = 64; s > 0; s >>= 1) {
        if (t < s) red[t] += red[t + s];
        __syncthreads();
    }
    float inv = 1.0f / red[0];
    __syncthreads();
    for (int i = t; i < NI; i += 128) g_c[i * NJ + j] = sb[i] * inv;
}

// ---------------------------------------------------------------------------
// Kernel 3: s[b,jd] = sum_i c[i,j] * U[b,jd,i]
// One warp per (b,jd): 40,960 warps, contiguous-i streaming.
// ---------------------------------------------------------------------------
__global__ __launch_bounds__(256) void s_kernel() {
    const int gw   = (blockIdx.x * blockDim.x + threadIdx.x) >> 5;
    const int lane = threadIdx.x & 31;
    if (gw >= NB * NJD) return;
    const int jd = gw % NJD;
    const int j  = jd >> 4;

    const float* up = g_U + (size_t)gw * NI;
    float acc = 0.f;
    for (int i0 = 0; i0 < NI; i0 += 128) {
#pragma unroll
        for (int k = 0; k < 4; k++) {
            int i = i0 + k * 32 + lane;
            acc = fmaf(up[i], __ldg(&g_c[i * NJ + j]), acc);
        }
    }
#pragma unroll
    for (int o = 16; o > 0; o >>= 1) acc += __shfl_down_sync(0xffffffffu, acc, o);
    if (lane == 0) g_s[gw] = acc;
}

// ---------------------------------------------------------------------------
// Kernel 4: squash. Norm over j (axis=1 of (B,j,d), faithful to reference):
//   msq[b,d] = sum_j s[b,j,d]^2 ;  v = s * sqrt(msq)/(1+msq)
// One thread per (b,d). Last iteration writes directly to d_out.
// ---------------------------------------------------------------------------
__global__ void squash_kernel(float* __restrict__ dst) {
    const int t = blockIdx.x * blockDim.x + threadIdx.x;
    if (t >= NB * ND) return;
    const int b = t >> 4, d = t & 15;
    float* v = dst ? dst : g_v;

    const float* sp = g_s + b * NJD + d;
    float vals[NJ];
    float msq = 0.f;
#pragma unroll
    for (int j = 0; j < NJ; j++) {
        vals[j] = sp[j * ND];
        msq = fmaf(vals[j], vals[j], msq);
    }
    float scale = sqrtf(msq) / (1.0f + msq);
#pragma unroll
    for (int j = 0; j < NJ; j++) v[b * NJD + j * ND + d] = vals[j] * scale;
}

// ---------------------------------------------------------------------------
// Kernel 5: agreement. uv[i,j] += sum_{b,d} U[b,j*16+d,i] * v[b,j,d]
// grid (9 i-blocks, 10 j, 8 b-chunks), block 128 (thread = one i).
// 16 independent loads per b step (MLP=16); v tile staged in smem.
// ---------------------------------------------------------------------------
__global__ __launch_bounds__(128) void agree_kernel() {
    const int i  = blockIdx.x * 128 + threadIdx.x;
    const int j  = blockIdx.y;
    const int bc = blockIdx.z;
    const int t  = threadIdx.x;

    __shared__ float vs[32 * ND];
    for (int k = t; k < 32 * ND; k += 128) {
        int bl = k >> 4, d = k & 15;
        vs[k] = g_v[(bc * 32 + bl) * NJD + j * ND + d];
    }
    __syncthreads();

    const float* up = g_U + ((size_t)(bc * 32) * NJD + j * ND) * NI + i;
    float acc = 0.f;
#pragma unroll 1
    for (int bl = 0; bl < 32; bl++) {
#pragma unroll
        for (int d = 0; d < ND; d++) {
            acc = fmaf(up[(size_t)d * NI], vs[bl * ND + d], acc);
        }
        up += (size_t)NJD * NI;
    }
    atomicAdd(&g_uv[i * NJ + j], acc);
}

// ---------------------------------------------------------------------------
extern "C" void kernel_launch(void* const* d_in, const int* in_sizes, int n_in,
                              void* d_out, int out_size) {
    const float* x = (const float*)d_in[0];   // (256, 8, 1152)
    const float* W = (const float*)d_in[1];   // (1, 1152, 10, 16, 8)
    float* out = (float*)d_out;               // (256, 10, 16, 1)

    uhat_kernel<<<dim3(36, 4, 4), 256>>>(x, W);

    for (int it = 0; it < 3; it++) {
        softmax_kernel<<<NJ, 128>>>(it == 0 ? 1 : 0);
        s_kernel<<<(NB * NJD) / 8, 256>>>();
        squash_kernel<<<16, 256>>>(it == 2 ? out : nullptr);
        if (it < 2) {
            agree_kernel<<<dim3(9, NJ, 8), 128>>>();
        }
    }
}

// round 3
// speedup vs baseline: 1.0406x; 1.0406x over previous
#include <cuda_runtime.h>
#include <cstddef>
#include <cstdint>

// Problem constants
#define NB   256            // batch
#define NU   8              // in_units
#define NI   1152           // in_size
#define NJ   10             // out_units
#define ND   16             // out_size
#define NJD  (NJ*ND)        // 160
#define NK   (NU*NI)        // 9216  flattened contraction dim (u,i)
#define NM   (NJD*NU)       // 1280  rows of W viewed as [i][jd*8+u]

// Scratch (device globals; allocation-free per harness rules)
__device__ float g_WT[(size_t)NJD * NU * NI];  // [jd][u][i]  5.9 MB
__device__ float g_G [(size_t)NJD * NU * NI];  // [jd][u][i]  5.9 MB
__device__ float g_s [NB * NJD];
__device__ float g_v [NB * NJD];
__device__ float g_b [NI * NJ];
__device__ float g_cT[NJ * NI];                // coupling coeffs, transposed [j][i]
__device__ float g_uv[NI * NJ];

// ---------------------------------------------------------------------------
// Kernel 0 (once): WT[m][i] = W[i][m],  m = jd*8+u in [0,1280), i in [0,1152)
// 32x32 smem tile transpose. grid (36, 40), block (32, 8).
// ---------------------------------------------------------------------------
__global__ void prep_kernel(const float* __restrict__ W) {
    __shared__ float t[32][33];
    const int i0 = blockIdx.x * 32, m0 = blockIdx.y * 32;
    const int tx = threadIdx.x, ty = threadIdx.y;
#pragma unroll
    for (int r = 0; r < 4; r++) {
        int i = i0 + ty + 8 * r;
        t[ty + 8 * r][tx] = W[(size_t)i * NM + m0 + tx];
    }
    __syncthreads();
#pragma unroll
    for (int r = 0; r < 4; r++) {
        int m = m0 + ty + 8 * r;
        g_WT[(size_t)m * NI + i0 + tx] = t[tx][ty + 8 * r];
    }
}

// ---------------------------------------------------------------------------
// Kernel 1: routing softmax over i (per j), fused b-update; also zeros g_s
// for the upcoming split-K GEMM. grid 10, block 128.
// ---------------------------------------------------------------------------
__global__ void softmax_kernel(int init) {
    const int j = blockIdx.x;
    const int t = threadIdx.x;
    __shared__ float sb[NI];
    __shared__ float red[128];

    float mx = -1e30f;
    for (int i = t; i < NI; i += 128) {
        float bn = init ? 1.0f
                        : (g_b[i * NJ + j] + g_uv[i * NJ + j] * (1.0f / (float)NB));
        g_b[i * NJ + j] = bn;
        sb[i] = bn;
        mx = fmaxf(mx, bn);
    }
    red[t] = mx;
    __syncthreads();
    for (int s = 64; s > 0; s >>= 1) {
        if (t < s) red[t] = fmaxf(red[t], red[t + s]);
        __syncthreads();
    }
    mx = red[0];
    __syncthreads();

    float sum = 0.f;
    for (int i = t; i < NI; i += 128) {
        float e = expf(sb[i] - mx);
        sb[i] = e;
        sum += e;
    }
    red[t] = sum;
    __syncthreads();
    for (int s = 64; s > 0; s >>= 1) {
        if (t < s) red[t] += red[t + s];
        __syncthreads();
    }
    const float inv = 1.0f / red[0];
    __syncthreads();
    for (int i = t; i < NI; i += 128) g_cT[j * NI + i] = sb[i] * inv;

    // zero s (40960 floats over 10 blocks)
    for (int k = t; k < (NB * NJD) / NJ; k += 128)
        g_s[j * ((NB * NJD) / NJ) + k] = 0.0f;
}

// ---------------------------------------------------------------------------
// Kernel 2: s[b,jd] += sum_k x[b,k] * cT[j, i(k)] * WT[jd, k]
// GEMM M=256(b) x N=160(jd), K=9216, split-K x16 (chunk 576, never crosses a
// u-block since 576 | 1152). grid (4 btile, 4 jdtile, 16 ks), block 256.
// CTA tile 64b x 40jd; thread tile 2b x 5jd.
// ---------------------------------------------------------------------------
__global__ __launch_bounds__(256) void s_gemm(const float* __restrict__ x) {
    const int b0    = blockIdx.x * 64;
    const int jd0   = blockIdx.y * 40;
    const int k0    = blockIdx.z * 576;
    const int ibase = (blockIdx.z & 1) * 576;   // i offset within its u-block

    __shared__ float As[32][65];   // [k][b]
    __shared__ float Bs[32][41];   // [k][jd_local]

    const int t  = threadIdx.x;
    const int tx = t & 7;          // 8 jd-groups of 5
    const int ty = t >> 3;         // 32 b-groups of 2

    float acc[2][5] = {};

    for (int kb = 0; kb < 576; kb += 32) {
#pragma unroll
        for (int l = t; l < 2048; l += 256) {     // A: 32k x 64b
            int k = l & 31, b = l >> 5;
            As[k][b] = x[(size_t)(b0 + b) * NK + k0 + kb + k];
        }
#pragma unroll
        for (int l = t; l < 1280; l += 256) {     // B: 32k x 40jd, c fused
            int k = l & 31, r = l >> 5;
            int jd = jd0 + r;
            int i  = ibase + kb + k;
            Bs[k][r] = g_WT[(size_t)jd * NK + k0 + kb + k] *
                       g_cT[(jd >> 4) * NI + i];
        }
        __syncthreads();
#pragma unroll
        for (int kk = 0; kk < 32; kk++) {
            float a0 = As[kk][ty * 2];
            float a1 = As[kk][ty * 2 + 1];
#pragma unroll
            for (int q = 0; q < 5; q++) {
                float bv = Bs[kk][tx * 5 + q];
                acc[0][q] = fmaf(a0, bv, acc[0][q]);
                acc[1][q] = fmaf(a1, bv, acc[1][q]);
            }
        }
        __syncthreads();
    }

#pragma unroll
    for (int r = 0; r < 2; r++)
#pragma unroll
        for (int q = 0; q < 5; q++)
            atomicAdd(&g_s[(b0 + ty * 2 + r) * NJD + jd0 + tx * 5 + q], acc[r][q]);
}

// ---------------------------------------------------------------------------
// Kernel 3: squash. msq[b,d] = sum_j s[b,j,d]^2 ; v = s * sqrt(msq)/(1+msq)
// One thread per (b,d). Final iteration writes d_out (dst!=nullptr).
// ---------------------------------------------------------------------------
__global__ void squash_kernel(float* __restrict__ dst) {
    const int t = blockIdx.x * blockDim.x + threadIdx.x;
    if (t >= NB * ND) return;
    const int b = t >> 4, d = t & 15;
    float* v = dst ? dst : g_v;

    const float* sp = g_s + b * NJD + d;
    float vals[NJ];
    float msq = 0.f;
#pragma unroll
    for (int j = 0; j < NJ; j++) {
        vals[j] = sp[j * ND];
        msq = fmaf(vals[j], vals[j], msq);
    }
    const float scale = sqrtf(msq) / (1.0f + msq);
#pragma unroll
    for (int j = 0; j < NJ; j++) v[b * NJD + j * ND + d] = vals[j] * scale;
}

// ---------------------------------------------------------------------------
// Kernel 4: G[jd, (u,i)] = sum_b v[b,jd] * x[b,(u,i)]
// GEMM M=160(jd) x N=9216(u,i), K=256(b). grid (144 ntile, 4 mtile), block 256.
// CTA tile 40m x 64n; thread tile 5m x 2n (n strided by 32 for coalescing).
// ---------------------------------------------------------------------------
__global__ __launch_bounds__(256) void g_gemm(const float* __restrict__ x) {
    const int n0 = blockIdx.x * 64;
    const int m0 = blockIdx.y * 40;

    __shared__ float Xs[32][65];   // [k][n_local]
    __shared__ float Vs[32][41];   // [k][m_local]

    const int t  = threadIdx.x;
    const int tx = t & 31;         // n lanes
    const int ty = t >> 5;         // 8 m-groups of 5

    float acc[5][2] = {};

    for (int kb = 0; kb < NB; kb += 32) {
#pragma unroll
        for (int l = t; l < 2048; l += 256) {     // X: 32k x 64n
            int nl = l & 63, k = l >> 6;
            Xs[k][nl] = x[(size_t)(kb + k) * NK + n0 + nl];
        }
#pragma unroll
        for (int l = t; l < 1280; l += 256) {     // V: 32k x 40m
            int r = l % 40, k = l / 40;
            Vs[k][r] = g_v[(kb + k) * NJD + m0 + r];
        }
        __syncthreads();
#pragma unroll
        for (int kk = 0; kk < 32; kk++) {
            float x0 = Xs[kk][tx];
            float x1 = Xs[kk][tx + 32];
#pragma unroll
            for (int q = 0; q < 5; q++) {
                float vv = Vs[kk][ty * 5 + q];
                acc[q][0] = fmaf(vv, x0, acc[q][0]);
                acc[q][1] = fmaf(vv, x1, acc[q][1]);
            }
        }
        __syncthreads();
    }

#pragma unroll
    for (int q = 0; q < 5; q++) {
#pragma unroll
        for (int r = 0; r < 2; r++)
            g_G[(size_t)(m0 + ty * 5 + q) * NK + n0 + tx + 32 * r] = acc[q][r];
    }
}

// ---------------------------------------------------------------------------
// Kernel 5: uv[i,j] = sum_{d,u} WT[jd,u,i] * G[jd,u,i]
// grid (9 iblocks, 10 j), block 128. Fully coalesced; single owner per (i,j).
// ---------------------------------------------------------------------------
__global__ __launch_bounds__(128) void uv_reduce() {
    const int i = blockIdx.x * 128 + threadIdx.x;
    const int j = blockIdx.y;
    const size_t base = (size_t)j * 128 * NI + i;   // rows m2 = d*8+u
    float acc = 0.f;
#pragma unroll 8
    for (int m = 0; m < 128; m++) {
        acc = fmaf(g_WT[base + (size_t)m * NI], g_G[base + (size_t)m * NI], acc);
    }
    g_uv[i * NJ + j] = acc;
}

// ---------------------------------------------------------------------------
extern "C" void kernel_launch(void* const* d_in, const int* in_sizes, int n_in,
                              void* d_out, int out_size) {
    const float* x = (const float*)d_in[0];   // (256, 8, 1152)
    const float* W = (const float*)d_in[1];   // (1, 1152, 10, 16, 8)
    float* out = (float*)d_out;               // (256, 10, 16, 1)

    prep_kernel<<<dim3(36, 40), dim3(32, 8)>>>(W);

    for (int it = 0; it < 3; it++) {
        softmax_kernel<<<NJ, 128>>>(it == 0 ? 1 : 0);
        s_gemm<<<dim3(4, 4, 16), 256>>>(x);
        squash_kernel<<<16, 256>>>(it == 2 ? out : nullptr);
        if (it < 2) {
            g_gemm<<<dim3(144, 4), 256>>>(x);
            uv_reduce<<<dim3(9, NJ), 128>>>();
        }
    }
}

// round 4
// speedup vs baseline: 1.4625x; 1.4055x over previous
#include <cuda_runtime.h>
#include <cstddef>
#include <cstdint>

// Problem constants
#define NB   256            // batch
#define NU   8              // in_units
#define NI   1152           // in_size
#define NJ   10             // out_units
#define ND   16             // out_size
#define NJD  (NJ*ND)        // 160
#define NK   (NU*NI)        // 9216  flattened contraction dim (u,i)
#define NM   (NJD*NU)       // 1280  rows of W viewed as [i][jd*8+u]

// Packed fp32x2 helpers (Blackwell sm_103a)
#define FMA_F32X2(acc, a, b) \
    asm("fma.rn.f32x2 %0, %1, %2, %0;" : "+l"(acc) : "l"(a), "l"(b))
#define PACK_SPLAT(out, f) \
    asm("mov.b64 %0, {%1, %1};" : "=l"(out) : "r"(__float_as_uint(f)))
#define UNPACK2(lo, hi, in) \
    asm("mov.b64 {%0, %1}, %2;" : "=r"(lo), "=r"(hi) : "l"(in))

// Scratch (device globals; allocation-free per harness rules)
__device__ float g_WT[(size_t)NJD * NU * NI];  // [jd][u][i]  5.9 MB
__device__ float g_G [(size_t)NJD * NU * NI];  // [jd][u][i]  5.9 MB
__device__ float g_s [NB * NJD];
__device__ float g_v [NB * NJD];
__device__ float g_b [NI * NJ];
__device__ float g_cT[NJ * NI];                // coupling coeffs, transposed [j][i]
__device__ float g_uv[NI * NJ];

// ---------------------------------------------------------------------------
// Kernel 0 (once): WT[m][i] = W[i][m]
// ---------------------------------------------------------------------------
__global__ void prep_kernel(const float* __restrict__ W) {
    __shared__ float t[32][33];
    const int i0 = blockIdx.x * 32, m0 = blockIdx.y * 32;
    const int tx = threadIdx.x, ty = threadIdx.y;
#pragma unroll
    for (int r = 0; r < 4; r++) {
        int i = i0 + ty + 8 * r;
        t[ty + 8 * r][tx] = W[(size_t)i * NM + m0 + tx];
    }
    __syncthreads();
#pragma unroll
    for (int r = 0; r < 4; r++) {
        int m = m0 + ty + 8 * r;
        g_WT[(size_t)m * NI + i0 + tx] = t[tx][ty + 8 * r];
    }
}

// ---------------------------------------------------------------------------
// Kernel 1: routing softmax over i (per j), fused b-update; zeroes g_s.
// ---------------------------------------------------------------------------
__global__ void softmax_kernel(int init) {
    const int j = blockIdx.x;
    const int t = threadIdx.x;
    __shared__ float sb[NI];
    __shared__ float red[128];

    float mx = -1e30f;
    for (int i = t; i < NI; i += 128) {
        float bn = init ? 1.0f
                        : (g_b[i * NJ + j] + g_uv[i * NJ + j] * (1.0f / (float)NB));
        g_b[i * NJ + j] = bn;
        sb[i] = bn;
        mx = fmaxf(mx, bn);
    }
    red[t] = mx;
    __syncthreads();
    for (int s = 64; s > 0; s >>= 1) {
        if (t < s) red[t] = fmaxf(red[t], red[t + s]);
        __syncthreads();
    }
    mx = red[0];
    __syncthreads();

    float sum = 0.f;
    for (int i = t; i < NI; i += 128) {
        float e = expf(sb[i] - mx);
        sb[i] = e;
        sum += e;
    }
    red[t] = sum;
    __syncthreads();
    for (int s = 64; s > 0; s >>= 1) {
        if (t < s) red[t] += red[t + s];
        __syncthreads();
    }
    const float inv = 1.0f / red[0];
    __syncthreads();
    for (int i = t; i < NI; i += 128) g_cT[j * NI + i] = sb[i] * inv;

    for (int k = t; k < (NB * NJD) / NJ; k += 128)
        g_s[j * ((NB * NJD) / NJ) + k] = 0.0f;
}

// ---------------------------------------------------------------------------
// Kernel 2: s[b,jd] += sum_k x[b,k] * cT[j, i(k)] * WT[jd, k]
// M=256(b) x N=160(jd) x K=9216, split-K x36 (chunk 256).
// grid (2, 4, 36), block 256. CTA tile 128b x 40jd; thread 4b x 5jd.
// Double-buffered smem, gmem->reg prefetch, f32x2 FMAs (b-pairs).
// ---------------------------------------------------------------------------
__global__ __launch_bounds__(256) void s_gemm(const float* __restrict__ x) {
    __shared__ float As[2][32][132];   // [k][b]
    __shared__ float Bs[2][32][41];    // [k][jd_local]

    const int t   = threadIdx.x;
    const int tx  = t & 7;             // 8 jd-groups of 5
    const int ty  = t >> 3;            // 32 b-groups of 4
    const int b0  = blockIdx.x * 128;
    const int jd0 = blockIdx.y * 40;
    const int k0  = blockIdx.z * 256;

    unsigned long long acc2[2][5];
#pragma unroll
    for (int p = 0; p < 2; p++)
#pragma unroll
        for (int q = 0; q < 5; q++) acc2[p][q] = 0ULL;

    float4 af[4];
    float  bf[5];

    // fetch k-block kb into registers
    auto fetch = [&](int kb) {
        const int kbase = k0 + kb * 32;
#pragma unroll
        for (int r = 0; r < 4; r++) {
            int idx4 = t + 256 * r;                   // over 1024 float4s
            int bl = idx4 >> 3, k4 = idx4 & 7;
            af[r] = *(const float4*)&x[(size_t)(b0 + bl) * NK + kbase + k4 * 4];
        }
#pragma unroll
        for (int r = 0; r < 5; r++) {
            int idx = t + 256 * r;                    // over 1280
            int kk = idx & 31, col = idx >> 5;
            int kg = kbase + kk;
            int u  = kg / NI;
            int i  = kg - u * NI;
            int jd = jd0 + col;
            bf[r] = g_WT[(size_t)jd * NK + kg] * g_cT[(jd >> 4) * NI + i];
        }
    };
    auto sts = [&](int buf) {
#pragma unroll
        for (int r = 0; r < 4; r++) {
            int idx4 = t + 256 * r;
            int bl = idx4 >> 3, k4 = idx4 & 7;
            As[buf][k4 * 4 + 0][bl] = af[r].x;
            As[buf][k4 * 4 + 1][bl] = af[r].y;
            As[buf][k4 * 4 + 2][bl] = af[r].z;
            As[buf][k4 * 4 + 3][bl] = af[r].w;
        }
#pragma unroll
        for (int r = 0; r < 5; r++) {
            int idx = t + 256 * r;
            Bs[buf][idx & 31][idx >> 5] = bf[r];
        }
    };

    fetch(0);
    sts(0);
    __syncthreads();

    for (int kb = 0; kb < 8; kb++) {
        const int buf = kb & 1;
        if (kb < 7) fetch(kb + 1);
#pragma unroll
        for (int kk = 0; kk < 32; kk++) {
            ulonglong2 aa = *(const ulonglong2*)&As[buf][kk][ty * 4];
#pragma unroll
            for (int q = 0; q < 5; q++) {
                float bv = Bs[buf][kk][tx * 5 + q];
                unsigned long long bb;
                PACK_SPLAT(bb, bv);
                FMA_F32X2(acc2[0][q], aa.x, bb);
                FMA_F32X2(acc2[1][q], aa.y, bb);
            }
        }
        if (kb < 7) {
            sts(buf ^ 1);
            __syncthreads();
        }
    }

#pragma unroll
    for (int p = 0; p < 2; p++)
#pragma unroll
        for (int q = 0; q < 5; q++) {
            unsigned lo, hi;
            UNPACK2(lo, hi, acc2[p][q]);
            int jd = jd0 + tx * 5 + q;
            atomicAdd(&g_s[(b0 + ty * 4 + 2 * p) * NJD + jd], __uint_as_float(lo));
            atomicAdd(&g_s[(b0 + ty * 4 + 2 * p + 1) * NJD + jd], __uint_as_float(hi));
        }
}

// ---------------------------------------------------------------------------
// Kernel 3: squash. msq[b,d] = sum_j s[b,j,d]^2 ; v = s * sqrt(msq)/(1+msq)
// ---------------------------------------------------------------------------
__global__ void squash_kernel(float* __restrict__ dst) {
    const int t = blockIdx.x * blockDim.x + threadIdx.x;
    if (t >= NB * ND) return;
    const int b = t >> 4, d = t & 15;
    float* v = dst ? dst : g_v;

    const float* sp = g_s + b * NJD + d;
    float vals[NJ];
    float msq = 0.f;
#pragma unroll
    for (int j = 0; j < NJ; j++) {
        vals[j] = sp[j * ND];
        msq = fmaf(vals[j], vals[j], msq);
    }
    const float scale = sqrtf(msq) / (1.0f + msq);
#pragma unroll
    for (int j = 0; j < NJ; j++) v[b * NJD + j * ND + d] = vals[j] * scale;
}

// ---------------------------------------------------------------------------
// Kernel 4: G[jd, n] = sum_b v[b,jd] * x[b,n]   (n = (u,i))
// M=160(jd) x N=9216 x K=256. grid (72, 4), block 256.
// CTA tile 40m x 128n; thread 5m x 4n. f32x2 FMAs (n-pairs).
// ---------------------------------------------------------------------------
__global__ __launch_bounds__(256) void g_gemm(const float* __restrict__ x) {
    __shared__ float Xs[2][32][132];   // [k][n_local]
    __shared__ float Vs[2][32][41];    // [k][m_local]

    const int t  = threadIdx.x;
    const int tx = t & 31;             // n-groups of 4
    const int ty = t >> 5;             // 8 m-groups of 5
    const int n0 = blockIdx.x * 128;
    const int m0 = blockIdx.y * 40;

    unsigned long long acc2[5][2];
#pragma unroll
    for (int q = 0; q < 5; q++)
#pragma unroll
        for (int p = 0; p < 2; p++) acc2[q][p] = 0ULL;

    float4 xf[4];
    float  vf[5];

    auto fetch = [&](int kb) {
        const int kbase = kb * 32;
#pragma unroll
        for (int r = 0; r < 4; r++) {
            int idx4 = t + 256 * r;                 // 1024 float4s = 32k x 32n4
            int kk = idx4 >> 5, n4 = idx4 & 31;
            xf[r] = *(const float4*)&x[(size_t)(kbase + kk) * NK + n0 + n4 * 4];
        }
#pragma unroll
        for (int r = 0; r < 5; r++) {
            int idx = t + 256 * r;                  // 1280
            int kk = idx / 40, col = idx % 40;
            vf[r] = g_v[(kbase + kk) * NJD + m0 + col];
        }
    };
    auto sts = [&](int buf) {
#pragma unroll
        for (int r = 0; r < 4; r++) {
            int idx4 = t + 256 * r;
            int kk = idx4 >> 5, n4 = idx4 & 31;
            *(float4*)&Xs[buf][kk][n4 * 4] = xf[r];
        }
#pragma unroll
        for (int r = 0; r < 5; r++) {
            int idx = t + 256 * r;
            Vs[buf][idx / 40][idx % 40] = vf[r];
        }
    };

    fetch(0);
    sts(0);
    __syncthreads();

    for (int kb = 0; kb < 8; kb++) {
        const int buf = kb & 1;
        if (kb < 7) fetch(kb + 1);
#pragma unroll
        for (int kk = 0; kk < 32; kk++) {
            ulonglong2 xx = *(const ulonglong2*)&Xs[buf][kk][tx * 4];
#pragma unroll
            for (int q = 0; q < 5; q++) {
                float vv = Vs[buf][kk][ty * 5 + q];
                unsigned long long vb;
                PACK_SPLAT(vb, vv);
                FMA_F32X2(acc2[q][0], xx.x, vb);
                FMA_F32X2(acc2[q][1], xx.y, vb);
            }
        }
        if (kb < 7) {
            sts(buf ^ 1);
            __syncthreads();
        }
    }

#pragma unroll
    for (int q = 0; q < 5; q++) {
        unsigned l0, h0, l1, h1;
        UNPACK2(l0, h0, acc2[q][0]);
        UNPACK2(l1, h1, acc2[q][1]);
        float4 o;
        o.x = __uint_as_float(l0);
        o.y = __uint_as_float(h0);
        o.z = __uint_as_float(l1);
        o.w = __uint_as_float(h1);
        *(float4*)&g_G[(size_t)(m0 + ty * 5 + q) * NK + n0 + tx * 4] = o;
    }
}

// ---------------------------------------------------------------------------
// Kernel 5: uv[i,j] = sum_{m=0..127} WT[j*128+m, i] * G[j*128+m, i]
// ---------------------------------------------------------------------------
__global__ __launch_bounds__(128) void uv_reduce() {
    const int i = blockIdx.x * 128 + threadIdx.x;
    const int j = blockIdx.y;
    const size_t base = (size_t)j * 128 * NI + i;
    float acc = 0.f;
#pragma unroll 8
    for (int m = 0; m < 128; m++) {
        acc = fmaf(g_WT[base + (size_t)m * NI], g_G[base + (size_t)m * NI], acc);
    }
    g_uv[i * NJ + j] = acc;
}

// ---------------------------------------------------------------------------
extern "C" void kernel_launch(void* const* d_in, const int* in_sizes, int n_in,
                              void* d_out, int out_size) {
    const float* x = (const float*)d_in[0];   // (256, 8, 1152)
    const float* W = (const float*)d_in[1];   // (1, 1152, 10, 16, 8)
    float* out = (float*)d_out;               // (256, 10, 16, 1)

    prep_kernel<<<dim3(36, 40), dim3(32, 8)>>>(W);

    for (int it = 0; it < 3; it++) {
        softmax_kernel<<<NJ, 128>>>(it == 0 ? 1 : 0);
        s_gemm<<<dim3(2, 4, 36), 256>>>(x);
        squash_kernel<<<16, 256>>>(it == 2 ? out : nullptr);
        if (it < 2) {
            g_gemm<<<dim3(72, 4), 256>>>(x);
            uv_reduce<<<dim3(9, NJ), 128>>>();
        }
    }
}